// round 10
// baseline (speedup 1.0000x reference)
#include <cuda_runtime.h>
#include <stdint.h>

#define BB 8
#define SS 2047
#define RT 1162
#define ROWS (BB * SS)
#define NEGF (-1e9f)
#define CH 128
#define NCH 16

// FINAL inclusive prefix per (b, j), padded to 2048 rows per batch.
// words 0..4 = instrument-present bitset (129 bits),
// word 5 = key_sign:  flag<<31 | j<<8 | value   (max selects latest; value inline)
// word 6 = time_sign: same encoding
// word 7 = tempo:     j<<8 | value, element j==0 always seeds its value
//          (matches jnp.argmax-of-zeros -> song[b,0,feat] semantics).
__device__ uint32_t g_prefix[(size_t)BB * 2048 * 8];
__device__ uint32_t g_agg[BB * NCH * 8];
// Monotone per-slot launch counters (never reset; graph replays serialize,
// so at each launch start all flags equal the replay index k; each block
// increments its own slot exactly once per launch).
__device__ int g_flag[BB * NCH];

__constant__ int c_num[12] = {1, 2, 3, 4, 5, 6, 7, 8, 9, 10, 12, 16};

__device__ __forceinline__ uint32_t pmax(uint32_t a, uint32_t b) { return a > b ? a : b; }

// Single-launch scan with decoupled lookback (no chaining): 128 blocks
// (8 batches x 16 chunks) x 128 threads, one element/thread, one wave.
__global__ __launch_bounds__(128) void scan_lookback(const int* __restrict__ song) {
    int b = blockIdx.x >> 4;
    int c = blockIdx.x & 15;
    int tid = threadIdx.x, lane = tid & 31, warp = tid >> 5;
    int j = c * CH + tid;
    int slot = b * NCH + c;

    __shared__ int s_epoch;
    __shared__ uint32_t s_carry[8];
    if (tid == 0) {
        s_epoch = ((volatile int*)g_flag)[slot];   // == launch index k (own block
                                                   // hasn't published yet)
#pragma unroll
        for (int k = 0; k < 8; ++k) s_carry[k] = 0;
    }

    uint32_t S[8] = {0, 0, 0, 0, 0, 0, 0, 0};
    if (j < SS) {
        const int* e = song + ((size_t)b * SS + j) * 11;
        int ty = e[0];                 // all 5 loads issued together (MLP)
        int v6 = e[6];
        int v8 = e[8];
        int v9 = e[9];
        int v10 = e[10];
        if (ty == 1) {
            S[v6 >> 5] |= 1u << (v6 & 31);
        } else if (ty == 4) {
            S[5] = 0x80000000u | ((uint32_t)j << 8) | (uint32_t)v8;
        } else if (ty == 5) {
            S[6] = 0x80000000u | ((uint32_t)j << 8) | (uint32_t)v9;
        } else if (ty == 6) {
            S[7] = ((uint32_t)j << 8) | (uint32_t)v10;
        }
        if (j == 0) {   // seed: no-match default is index 0 -> its value
            S[5] = pmax(S[5], (uint32_t)v8);
            S[6] = pmax(S[6], (uint32_t)v9);
            S[7] = pmax(S[7], (uint32_t)v10);
        }
    }

    // warp-inclusive shuffle scan (combine is commutative: OR / max)
#pragma unroll
    for (int d = 1; d < 32; d <<= 1) {
        uint32_t o[8];
#pragma unroll
        for (int w = 0; w < 8; ++w) o[w] = __shfl_up_sync(0xffffffffu, S[w], d);
        if (lane >= d) {
            S[0] |= o[0]; S[1] |= o[1]; S[2] |= o[2]; S[3] |= o[3]; S[4] |= o[4];
            S[5] = pmax(S[5], o[5]); S[6] = pmax(S[6], o[6]); S[7] = pmax(S[7], o[7]);
        }
    }

    __shared__ uint32_t agg[4][8];
    if (lane == 31) {
#pragma unroll
        for (int w = 0; w < 8; ++w) agg[warp][w] = S[w];
    }
    __syncthreads();   // also orders s_epoch / s_carry init
#pragma unroll
    for (int w2 = 0; w2 < 3; ++w2) {
        if (warp > w2) {
            S[0] |= agg[w2][0]; S[1] |= agg[w2][1]; S[2] |= agg[w2][2];
            S[3] |= agg[w2][3]; S[4] |= agg[w2][4];
            S[5] = pmax(S[5], agg[w2][5]);
            S[6] = pmax(S[6], agg[w2][6]);
            S[7] = pmax(S[7], agg[w2][7]);
        }
    }
    // S = chunk-local inclusive prefix at position tid.

    // --- publish local aggregate (last valid thread of the chunk) ---
    int lastt = (c == NCH - 1) ? (SS - 1 - c * CH) : (CH - 1);
    if (tid == lastt) {
        uint4* a = (uint4*)&g_agg[slot * 8];
        a[0] = make_uint4(S[0], S[1], S[2], S[3]);
        a[1] = make_uint4(S[4], S[5], S[6], S[7]);
        __threadfence();
        atomicAdd(&g_flag[slot], 1);
    }

    // --- lookback: warp 0, lane l (< c) spins on predecessor chunk l ---
    if (warp == 0) {
        int ep = s_epoch;
        uint32_t A[8] = {0, 0, 0, 0, 0, 0, 0, 0};
        if (lane < c) {
            int ps = b * NCH + lane;
            while (((volatile int*)g_flag)[ps] <= ep) { }
            __threadfence();
            const uint4* a = (const uint4*)&g_agg[ps * 8];
            uint4 a0 = a[0], a1 = a[1];
            A[0] = a0.x; A[1] = a0.y; A[2] = a0.z; A[3] = a0.w;
            A[4] = a1.x; A[5] = a1.y; A[6] = a1.z; A[7] = a1.w;
        }
        // reduce lanes 0..15 (lanes >= c contribute identity)
#pragma unroll
        for (int d = 8; d; d >>= 1) {
            uint32_t o[8];
#pragma unroll
            for (int w = 0; w < 8; ++w) o[w] = __shfl_down_sync(0xffffffffu, A[w], d, 16);
            A[0] |= o[0]; A[1] |= o[1]; A[2] |= o[2]; A[3] |= o[3]; A[4] |= o[4];
            A[5] = pmax(A[5], o[5]); A[6] = pmax(A[6], o[6]); A[7] = pmax(A[7], o[7]);
        }
        if (lane == 0 && c > 0) {
#pragma unroll
            for (int w = 0; w < 8; ++w) s_carry[w] = A[w];
        }
    }
    __syncthreads();

    // --- fold carry, store FINAL inclusive prefix ---
    if (j < SS) {
        uint32_t f0 = S[0] | s_carry[0], f1 = S[1] | s_carry[1];
        uint32_t f2 = S[2] | s_carry[2], f3 = S[3] | s_carry[3];
        uint32_t f4 = S[4] | s_carry[4];
        uint32_t f5 = pmax(S[5], s_carry[5]);
        uint32_t f6 = pmax(S[6], s_carry[6]);
        uint32_t f7 = pmax(S[7], s_carry[7]);
        uint4* dst = (uint4*)&g_prefix[((size_t)b * 2048 + j) * 8];
        dst[0] = make_uint4(f0, f1, f2, f3);
        dst[1] = make_uint4(f4, f5, f6, f7);
    }
}

// Warp per row: prefix loads issued early, argmax overlaps them, then copy +
// sparse overwrites. No block barrier. (Identical to R9's apply.)
__global__ __launch_bounds__(256) void apply_kernel(const int* __restrict__ song,
                                                    const int* __restrict__ chosen,
                                                    const float* __restrict__ scores,
                                                    float* __restrict__ out) {
    int warp = threadIdx.x >> 5;
    int lane = threadIdx.x & 31;
    int row = blockIdx.x * 8 + warp;      // grid = 2047 -> 16376 rows exactly
    int b = row / SS;
    int i = row - b * SS;
    const float* srow = scores + (size_t)row * RT;
    float* orow = out + (size_t)row * RT;

    __shared__ int sp_all[8][16];
    int* sp = sp_all[warp];

    // --- lane 0: issue all scalar loads FIRST (independent of the argmax) ---
    uint4 p0, p1;
    int sm1 = 0, sb2 = 0, sp3 = 0, tcho = 0;
    if (lane == 0) {
        int jj = (i + 1 < SS) ? i + 1 : SS - 1;
        const uint4* PL = (const uint4*)&g_prefix[((size_t)b * 2048 + jj) * 8];
        p0 = PL[0]; p1 = PL[1];
        const int* si = song + (size_t)row * 11;
        sm1 = si[1]; sb2 = si[2]; sp3 = si[3];
        tcho = chosen[row];
    }

    // --- measure argmax over scores[0:256] (first-index tiebreak = jnp.argmax) ---
    float bv = srow[lane];
    int bi = lane;
#pragma unroll
    for (int k = 1; k < 8; ++k) {
        float v = srow[lane + 32 * k];
        if (v > bv) { bv = v; bi = lane + 32 * k; }
    }
#pragma unroll
    for (int d = 16; d; d >>= 1) {
        float ov = __shfl_down_sync(0xffffffffu, bv, d);
        int oi = __shfl_down_sync(0xffffffffu, bi, d);
        if (ov > bv || (ov == bv && oi < bi)) { bv = ov; bi = oi; }
    }
    int pred_m = bi;   // valid on lane 0

    // --- beat argmax over scores[256:272] ---
    float bb = srow[256 + (lane & 15)];
    int bj = lane & 15;
#pragma unroll
    for (int d = 8; d; d >>= 1) {
        float ov = __shfl_down_sync(0xffffffffu, bb, d, 16);
        int oj = __shfl_down_sync(0xffffffffu, bj, d, 16);
        if (ov > bb || (ov == bb && oj < bj)) { bb = ov; bj = oj; }
    }
    int pred_b = bj;   // valid on lane 0

    if (lane == 0) {
        uint32_t w0 = p0.x, w1 = p0.y, w2 = p0.z, w3 = p0.w, w4 = p1.x;
        uint32_t wk = p1.y, wt = p1.z, wp = p1.w;

        int last_ks = (int)(wk & 0xffu);
        int last_ts = (int)(wt & 0xffu);
        int last_tp = (int)(wp & 0xffu);
        bool has_ks = (wk >> 31) != 0;
        bool has_ts = (wt >> 31) != 0;
        int max_beat = c_num[last_ts % 12];

        bool c1f = (pred_m == sm1);
        int min_beat = c1f ? sb2 : 0;
        bool c2f = c1f && (pred_b == min_beat);
        int min_pos = c2f ? sp3 : 0;
        int min_m46 = (sb2 == 0 && sp3 == 0) ? sm1 : sm1 + 1;
        bool has_inst = (w0 | w1 | w2 | w3 | w4) != 0;
        bool is3 = (tcho == 3);

        sp[0] = (int)w0; sp[1] = (int)w1; sp[2] = (int)w2;
        sp[3] = (int)w3; sp[4] = (int)w4;
        sp[5] = is3 ? sm1 : ((tcho >= 4 && tcho <= 6) ? min_m46 : 0);
        sp[6] = is3 ? min_beat : 0;
        sp[7] = is3 ? max_beat : 16;
        sp[8] = is3 ? min_pos : 0;
        sp[9] = is3 ? 1 : ((tcho == 1 && has_inst) ? 2 : 0);
        sp[10] = is3 ? 1 : ((tcho == 4 && has_ks) ? 2 : 0);
        sp[11] = last_ks;
        sp[12] = is3 ? 1 : ((tcho == 5 && has_ts) ? 2 : 0);
        sp[13] = last_ts;
        sp[14] = is3 ? 1 : ((tcho == 6) ? 2 : 0);
        sp[15] = last_tp;
    }

    // --- float4 copy (row byte offset = row*4648; 16B-aligned iff row even) ---
    if ((row & 1) == 0) {
        const float4* s4 = (const float4*)srow;
        float4* o4 = (float4*)orow;
#pragma unroll
        for (int p = lane; p < 290; p += 32) o4[p] = s4[p];    // floats 0..1159
        if (lane == 0) *(float2*)(orow + 1160) = *(const float2*)(srow + 1160);
    } else {
        const float4* s4 = (const float4*)(srow + 2);
        float4* o4 = (float4*)(orow + 2);
#pragma unroll
        for (int p = lane; p < 290; p += 32) o4[p] = s4[p];    // floats 2..1161
        if (lane == 0) *(float2*)orow = *(const float2*)srow;
    }
    __syncwarp();

    // --- sparse overwrites (lane-strided) ---
    int mth = sp[5], blo = sp[6], bhi = sp[7], pth = sp[8];
    int imode = sp[9], kmode = sp[10], kval = sp[11];
    int tsm = sp[12], tsv = sp[13], tpm = sp[14], tpv = sp[15];

    for (int c = lane; c < mth; c += 32) orow[c] = NEGF;                 // measure
    if (lane < 16 && (lane < blo || lane >= bhi)) orow[256 + lane] = NEGF;  // beat
    for (int p = lane; p < pth; p += 32) orow[272 + p] = NEGF;           // position
    if (imode) {                                                          // instrument
#pragma unroll
        for (int k = 0; k < 5; ++k) {
            int ci = lane + 32 * k;
            if (ci < 129) {
                bool pres = ((uint32_t)sp[k] >> lane) & 1u;
                bool masked = (imode == 1) ? !pres : pres;
                if (masked) orow[784 + ci] = NEGF;
            }
        }
    }
    if (kmode && lane < 24) {                                             // key_sign
        bool masked = (kmode == 1) ? (lane != kval) : (lane == kval);
        if (masked) orow[1041 + lane] = NEGF;
    }
    if (tsm) {                                                            // time_sign
#pragma unroll
        for (int k = 0; k < 2; ++k) {
            int ct = lane + 32 * k;
            if (ct < 48) {
                bool masked = (tsm == 1) ? (ct != tsv) : (ct == tsv);
                if (masked) orow[1065 + ct] = NEGF;
            }
        }
    }
    if (tpm) {                                                            // tempo
#pragma unroll
        for (int k = 0; k < 2; ++k) {
            int cp = lane + 32 * k;
            if (cp < 49) {
                bool masked = (tpm == 1) ? (cp != tpv) : (cp == tpv);
                if (masked) orow[1113 + cp] = NEGF;
            }
        }
    }
}

extern "C" void kernel_launch(void* const* d_in, const int* in_sizes, int n_in,
                              void* d_out, int out_size) {
    const int* song = (const int*)d_in[0];
    const int* chosen = (const int*)d_in[1];
    const float* scores = (const float*)d_in[2];
    float* out = (float*)d_out;

    scan_lookback<<<BB * NCH, CH>>>(song);
    apply_kernel<<<ROWS / 8, 256>>>(song, chosen, scores, out);
}

// round 11
// speedup vs baseline: 1.1043x; 1.1043x over previous
#include <cuda_runtime.h>
#include <stdint.h>

#define BB 8
#define SS 2047
#define RT 1162
#define ROWS (BB * SS)
#define NEGF (-1e9f)
#define CH 128
#define NCH 16

// Prefix per (b, j), padded to 2048 rows per batch. After fold_carry it is the
// FINAL inclusive prefix.
// words 0..4 = instrument-present bitset (129 bits),
// word 5 = key_sign:  flag<<31 | j<<8 | value   (max selects latest; value inline)
// word 6 = time_sign: same encoding
// word 7 = tempo:     j<<8 | value, element j==0 always seeds its value
//          (matches jnp.argmax-of-zeros -> song[b,0,feat] semantics).
__device__ uint32_t g_prefix[(size_t)BB * 2048 * 8];
__device__ uint32_t g_agg[BB * NCH * 8];

__constant__ int c_num[12] = {1, 2, 3, 4, 5, 6, 7, 8, 9, 10, 12, 16};

__device__ __forceinline__ uint32_t pmax(uint32_t a, uint32_t b) { return a > b ? a : b; }

// 128 blocks (8 batches x 16 chunks) x 128 threads, 1 element/thread.
// All song fields loaded unconditionally up-front (MLP=5, no dependent chain).
__global__ __launch_bounds__(128) void scan_local(const int* __restrict__ song) {
    int b = blockIdx.x >> 4;
    int c = blockIdx.x & 15;
    int tid = threadIdx.x, lane = tid & 31, warp = tid >> 5;
    int j = c * CH + tid;

    uint32_t S[8] = {0, 0, 0, 0, 0, 0, 0, 0};
    if (j < SS) {
        const int* e = song + ((size_t)b * SS + j) * 11;
        int ty = e[0];                 // all 5 loads issued together
        int v6 = e[6];
        int v8 = e[8];
        int v9 = e[9];
        int v10 = e[10];
        if (ty == 1) {
            S[v6 >> 5] |= 1u << (v6 & 31);
        } else if (ty == 4) {
            S[5] = 0x80000000u | ((uint32_t)j << 8) | (uint32_t)v8;
        } else if (ty == 5) {
            S[6] = 0x80000000u | ((uint32_t)j << 8) | (uint32_t)v9;
        } else if (ty == 6) {
            S[7] = ((uint32_t)j << 8) | (uint32_t)v10;
        }
        if (j == 0) {   // seed: no-match default is index 0 -> its value
            S[5] = pmax(S[5], (uint32_t)v8);
            S[6] = pmax(S[6], (uint32_t)v9);
            S[7] = pmax(S[7], (uint32_t)v10);
        }
    }

    // warp-inclusive shuffle scan (combine is commutative: OR / max)
#pragma unroll
    for (int d = 1; d < 32; d <<= 1) {
        uint32_t o[8];
#pragma unroll
        for (int w = 0; w < 8; ++w) o[w] = __shfl_up_sync(0xffffffffu, S[w], d);
        if (lane >= d) {
            S[0] |= o[0]; S[1] |= o[1]; S[2] |= o[2]; S[3] |= o[3]; S[4] |= o[4];
            S[5] = pmax(S[5], o[5]); S[6] = pmax(S[6], o[6]); S[7] = pmax(S[7], o[7]);
        }
    }

    __shared__ uint32_t agg[4][8];
    if (lane == 31) {
#pragma unroll
        for (int w = 0; w < 8; ++w) agg[warp][w] = S[w];
    }
    __syncthreads();
#pragma unroll
    for (int w2 = 0; w2 < 3; ++w2) {
        if (warp > w2) {
            S[0] |= agg[w2][0]; S[1] |= agg[w2][1]; S[2] |= agg[w2][2];
            S[3] |= agg[w2][3]; S[4] |= agg[w2][4];
            S[5] = pmax(S[5], agg[w2][5]);
            S[6] = pmax(S[6], agg[w2][6]);
            S[7] = pmax(S[7], agg[w2][7]);
        }
    }

    if (j < SS) {
        uint4* dst = (uint4*)&g_prefix[((size_t)b * 2048 + j) * 8];
        dst[0] = make_uint4(S[0], S[1], S[2], S[3]);
        dst[1] = make_uint4(S[4], S[5], S[6], S[7]);
    }
    int lastt = (c == NCH - 1) ? (SS - 1 - c * CH) : (CH - 1);
    if (tid == lastt) {
        uint4* a = (uint4*)&g_agg[(b * NCH + c) * 8];
        a[0] = make_uint4(S[0], S[1], S[2], S[3]);
        a[1] = make_uint4(S[4], S[5], S[6], S[7]);
    }
}

// 120 blocks (8 batches x chunks 1..15) x 128 threads. Each block reduces its
// chunk's predecessor aggregates (redundant, cheap) and folds the carry into
// its chunk's 128 prefix rows in place -> g_prefix becomes FINAL.
__global__ __launch_bounds__(128) void fold_carry() {
    int b = blockIdx.x / (NCH - 1);
    int c = blockIdx.x % (NCH - 1) + 1;    // 1..15
    int tid = threadIdx.x, lane = tid & 31, warp = tid >> 5;

    __shared__ uint32_t s_carry[8];

    if (warp == 0) {
        uint32_t A[8] = {0, 0, 0, 0, 0, 0, 0, 0};
        if (lane < c) {
            const uint4* a = (const uint4*)&g_agg[(b * NCH + lane) * 8];
            uint4 a0 = a[0], a1 = a[1];
            A[0] = a0.x; A[1] = a0.y; A[2] = a0.z; A[3] = a0.w;
            A[4] = a1.x; A[5] = a1.y; A[6] = a1.z; A[7] = a1.w;
        }
        // reduce lanes 0..15 (lanes >= c contribute identity)
#pragma unroll
        for (int d = 8; d; d >>= 1) {
            uint32_t o[8];
#pragma unroll
            for (int w = 0; w < 8; ++w) o[w] = __shfl_down_sync(0xffffffffu, A[w], d, 16);
            A[0] |= o[0]; A[1] |= o[1]; A[2] |= o[2]; A[3] |= o[3]; A[4] |= o[4];
            A[5] = pmax(A[5], o[5]); A[6] = pmax(A[6], o[6]); A[7] = pmax(A[7], o[7]);
        }
        if (lane == 0) {
#pragma unroll
            for (int w = 0; w < 8; ++w) s_carry[w] = A[w];
        }
    }
    __syncthreads();

    int j = c * CH + tid;
    if (j < SS) {
        uint4* dst = (uint4*)&g_prefix[((size_t)b * 2048 + j) * 8];
        uint4 p0 = dst[0], p1 = dst[1];
        p0.x |= s_carry[0]; p0.y |= s_carry[1]; p0.z |= s_carry[2]; p0.w |= s_carry[3];
        p1.x |= s_carry[4];
        p1.y = pmax(p1.y, s_carry[5]);
        p1.z = pmax(p1.z, s_carry[6]);
        p1.w = pmax(p1.w, s_carry[7]);
        dst[0] = p0;
        dst[1] = p1;
    }
}

// Warp per row: prefix loads issued early, argmax overlaps them, then copy +
// sparse overwrites. No block barrier. (Identical to R9's 24.4us apply.)
__global__ __launch_bounds__(256) void apply_kernel(const int* __restrict__ song,
                                                    const int* __restrict__ chosen,
                                                    const float* __restrict__ scores,
                                                    float* __restrict__ out) {
    int warp = threadIdx.x >> 5;
    int lane = threadIdx.x & 31;
    int row = blockIdx.x * 8 + warp;      // grid = 2047 -> 16376 rows exactly
    int b = row / SS;
    int i = row - b * SS;
    const float* srow = scores + (size_t)row * RT;
    float* orow = out + (size_t)row * RT;

    __shared__ int sp_all[8][16];
    int* sp = sp_all[warp];

    // --- lane 0: issue all scalar loads FIRST (independent of the argmax) ---
    uint4 p0, p1;
    int sm1 = 0, sb2 = 0, sp3 = 0, tcho = 0;
    if (lane == 0) {
        int jj = (i + 1 < SS) ? i + 1 : SS - 1;
        const uint4* PL = (const uint4*)&g_prefix[((size_t)b * 2048 + jj) * 8];
        p0 = PL[0]; p1 = PL[1];
        const int* si = song + (size_t)row * 11;
        sm1 = si[1]; sb2 = si[2]; sp3 = si[3];
        tcho = chosen[row];
    }

    // --- measure argmax over scores[0:256] (first-index tiebreak = jnp.argmax) ---
    float bv = srow[lane];
    int bi = lane;
#pragma unroll
    for (int k = 1; k < 8; ++k) {
        float v = srow[lane + 32 * k];
        if (v > bv) { bv = v; bi = lane + 32 * k; }
    }
#pragma unroll
    for (int d = 16; d; d >>= 1) {
        float ov = __shfl_down_sync(0xffffffffu, bv, d);
        int oi = __shfl_down_sync(0xffffffffu, bi, d);
        if (ov > bv || (ov == bv && oi < bi)) { bv = ov; bi = oi; }
    }
    int pred_m = bi;   // valid on lane 0

    // --- beat argmax over scores[256:272] ---
    float bb = srow[256 + (lane & 15)];
    int bj = lane & 15;
#pragma unroll
    for (int d = 8; d; d >>= 1) {
        float ov = __shfl_down_sync(0xffffffffu, bb, d, 16);
        int oj = __shfl_down_sync(0xffffffffu, bj, d, 16);
        if (ov > bb || (ov == bb && oj < bj)) { bb = ov; bj = oj; }
    }
    int pred_b = bj;   // valid on lane 0

    if (lane == 0) {
        uint32_t w0 = p0.x, w1 = p0.y, w2 = p0.z, w3 = p0.w, w4 = p1.x;
        uint32_t wk = p1.y, wt = p1.z, wp = p1.w;

        int last_ks = (int)(wk & 0xffu);
        int last_ts = (int)(wt & 0xffu);
        int last_tp = (int)(wp & 0xffu);
        bool has_ks = (wk >> 31) != 0;
        bool has_ts = (wt >> 31) != 0;
        int max_beat = c_num[last_ts % 12];

        bool c1f = (pred_m == sm1);
        int min_beat = c1f ? sb2 : 0;
        bool c2f = c1f && (pred_b == min_beat);
        int min_pos = c2f ? sp3 : 0;
        int min_m46 = (sb2 == 0 && sp3 == 0) ? sm1 : sm1 + 1;
        bool has_inst = (w0 | w1 | w2 | w3 | w4) != 0;
        bool is3 = (tcho == 3);

        sp[0] = (int)w0; sp[1] = (int)w1; sp[2] = (int)w2;
        sp[3] = (int)w3; sp[4] = (int)w4;
        sp[5] = is3 ? sm1 : ((tcho >= 4 && tcho <= 6) ? min_m46 : 0);
        sp[6] = is3 ? min_beat : 0;
        sp[7] = is3 ? max_beat : 16;
        sp[8] = is3 ? min_pos : 0;
        sp[9] = is3 ? 1 : ((tcho == 1 && has_inst) ? 2 : 0);
        sp[10] = is3 ? 1 : ((tcho == 4 && has_ks) ? 2 : 0);
        sp[11] = last_ks;
        sp[12] = is3 ? 1 : ((tcho == 5 && has_ts) ? 2 : 0);
        sp[13] = last_ts;
        sp[14] = is3 ? 1 : ((tcho == 6) ? 2 : 0);
        sp[15] = last_tp;
    }

    // --- float4 copy (row byte offset = row*4648; 16B-aligned iff row even) ---
    if ((row & 1) == 0) {
        const float4* s4 = (const float4*)srow;
        float4* o4 = (float4*)orow;
#pragma unroll
        for (int p = lane; p < 290; p += 32) o4[p] = s4[p];    // floats 0..1159
        if (lane == 0) *(float2*)(orow + 1160) = *(const float2*)(srow + 1160);
    } else {
        const float4* s4 = (const float4*)(srow + 2);
        float4* o4 = (float4*)(orow + 2);
#pragma unroll
        for (int p = lane; p < 290; p += 32) o4[p] = s4[p];    // floats 2..1161
        if (lane == 0) *(float2*)orow = *(const float2*)srow;
    }
    __syncwarp();

    // --- sparse overwrites (lane-strided) ---
    int mth = sp[5], blo = sp[6], bhi = sp[7], pth = sp[8];
    int imode = sp[9], kmode = sp[10], kval = sp[11];
    int tsm = sp[12], tsv = sp[13], tpm = sp[14], tpv = sp[15];

    for (int c = lane; c < mth; c += 32) orow[c] = NEGF;                 // measure
    if (lane < 16 && (lane < blo || lane >= bhi)) orow[256 + lane] = NEGF;  // beat
    for (int p = lane; p < pth; p += 32) orow[272 + p] = NEGF;           // position
    if (imode) {                                                          // instrument
#pragma unroll
        for (int k = 0; k < 5; ++k) {
            int ci = lane + 32 * k;
            if (ci < 129) {
                bool pres = ((uint32_t)sp[k] >> lane) & 1u;
                bool masked = (imode == 1) ? !pres : pres;
                if (masked) orow[784 + ci] = NEGF;
            }
        }
    }
    if (kmode && lane < 24) {                                             // key_sign
        bool masked = (kmode == 1) ? (lane != kval) : (lane == kval);
        if (masked) orow[1041 + lane] = NEGF;
    }
    if (tsm) {                                                            // time_sign
#pragma unroll
        for (int k = 0; k < 2; ++k) {
            int ct = lane + 32 * k;
            if (ct < 48) {
                bool masked = (tsm == 1) ? (ct != tsv) : (ct == tsv);
                if (masked) orow[1065 + ct] = NEGF;
            }
        }
    }
    if (tpm) {                                                            // tempo
#pragma unroll
        for (int k = 0; k < 2; ++k) {
            int cp = lane + 32 * k;
            if (cp < 49) {
                bool masked = (tpm == 1) ? (cp != tpv) : (cp == tpv);
                if (masked) orow[1113 + cp] = NEGF;
            }
        }
    }
}

extern "C" void kernel_launch(void* const* d_in, const int* in_sizes, int n_in,
                              void* d_out, int out_size) {
    const int* song = (const int*)d_in[0];
    const int* chosen = (const int*)d_in[1];
    const float* scores = (const float*)d_in[2];
    float* out = (float*)d_out;

    scan_local<<<BB * NCH, CH>>>(song);
    fold_carry<<<BB * (NCH - 1), CH>>>();
    apply_kernel<<<ROWS / 8, 256>>>(song, chosen, scores, out);
}

// round 12
// speedup vs baseline: 1.1247x; 1.0185x over previous
#include <cuda_runtime.h>
#include <stdint.h>

#define BB 8
#define SS 2047
#define RT 1162
#define ROWS (BB * SS)
#define NEGF (-1e9f)
#define CH 128
#define NCH 16

// Prefix per (b, j), padded to 2048 rows per batch. After fold_carry it is the
// FINAL inclusive prefix.
// words 0..4 = instrument-present bitset (129 bits),
// word 5 = key_sign:  flag<<31 | j<<8 | value   (max selects latest; value inline)
// word 6 = time_sign: same encoding
// word 7 = tempo:     j<<8 | value, element j==0 always seeds its value
//          (matches jnp.argmax-of-zeros -> song[b,0,feat] semantics).
__device__ uint32_t g_prefix[(size_t)BB * 2048 * 8];
__device__ uint32_t g_agg[BB * NCH * 8];

__constant__ int c_num[12] = {1, 2, 3, 4, 5, 6, 7, 8, 9, 10, 12, 16};

__device__ __forceinline__ uint32_t pmax(uint32_t a, uint32_t b) { return a > b ? a : b; }

// 128 blocks (8 batches x 16 chunks) x 128 threads, 1 element/thread.
__global__ __launch_bounds__(128) void scan_local(const int* __restrict__ song) {
    cudaTriggerProgrammaticLaunchCompletion();   // let successors launch early

    int b = blockIdx.x >> 4;
    int c = blockIdx.x & 15;
    int tid = threadIdx.x, lane = tid & 31, warp = tid >> 5;
    int j = c * CH + tid;

    uint32_t S[8] = {0, 0, 0, 0, 0, 0, 0, 0};
    if (j < SS) {
        const int* e = song + ((size_t)b * SS + j) * 11;
        int ty = e[0];                 // all 5 loads issued together (MLP)
        int v6 = e[6];
        int v8 = e[8];
        int v9 = e[9];
        int v10 = e[10];
        if (ty == 1) {
            S[v6 >> 5] |= 1u << (v6 & 31);
        } else if (ty == 4) {
            S[5] = 0x80000000u | ((uint32_t)j << 8) | (uint32_t)v8;
        } else if (ty == 5) {
            S[6] = 0x80000000u | ((uint32_t)j << 8) | (uint32_t)v9;
        } else if (ty == 6) {
            S[7] = ((uint32_t)j << 8) | (uint32_t)v10;
        }
        if (j == 0) {   // seed: no-match default is index 0 -> its value
            S[5] = pmax(S[5], (uint32_t)v8);
            S[6] = pmax(S[6], (uint32_t)v9);
            S[7] = pmax(S[7], (uint32_t)v10);
        }
    }

    // warp-inclusive shuffle scan (combine is commutative: OR / max)
#pragma unroll
    for (int d = 1; d < 32; d <<= 1) {
        uint32_t o[8];
#pragma unroll
        for (int w = 0; w < 8; ++w) o[w] = __shfl_up_sync(0xffffffffu, S[w], d);
        if (lane >= d) {
            S[0] |= o[0]; S[1] |= o[1]; S[2] |= o[2]; S[3] |= o[3]; S[4] |= o[4];
            S[5] = pmax(S[5], o[5]); S[6] = pmax(S[6], o[6]); S[7] = pmax(S[7], o[7]);
        }
    }

    __shared__ uint32_t agg[4][8];
    if (lane == 31) {
#pragma unroll
        for (int w = 0; w < 8; ++w) agg[warp][w] = S[w];
    }
    __syncthreads();
#pragma unroll
    for (int w2 = 0; w2 < 3; ++w2) {
        if (warp > w2) {
            S[0] |= agg[w2][0]; S[1] |= agg[w2][1]; S[2] |= agg[w2][2];
            S[3] |= agg[w2][3]; S[4] |= agg[w2][4];
            S[5] = pmax(S[5], agg[w2][5]);
            S[6] = pmax(S[6], agg[w2][6]);
            S[7] = pmax(S[7], agg[w2][7]);
        }
    }

    if (j < SS) {
        uint4* dst = (uint4*)&g_prefix[((size_t)b * 2048 + j) * 8];
        dst[0] = make_uint4(S[0], S[1], S[2], S[3]);
        dst[1] = make_uint4(S[4], S[5], S[6], S[7]);
    }
    int lastt = (c == NCH - 1) ? (SS - 1 - c * CH) : (CH - 1);
    if (tid == lastt) {
        uint4* a = (uint4*)&g_agg[(b * NCH + c) * 8];
        a[0] = make_uint4(S[0], S[1], S[2], S[3]);
        a[1] = make_uint4(S[4], S[5], S[6], S[7]);
    }
}

// 120 blocks (8 batches x chunks 1..15) x 128 threads. Folds carry into
// g_prefix in place -> FINAL. PDL: triggers at entry, syncs before reading.
__global__ __launch_bounds__(128) void fold_carry() {
    cudaTriggerProgrammaticLaunchCompletion();   // let apply launch early
    cudaGridDependencySynchronize();             // wait for scan_local results

    int b = blockIdx.x / (NCH - 1);
    int c = blockIdx.x % (NCH - 1) + 1;    // 1..15
    int tid = threadIdx.x, lane = tid & 31, warp = tid >> 5;

    __shared__ uint32_t s_carry[8];

    if (warp == 0) {
        uint32_t A[8] = {0, 0, 0, 0, 0, 0, 0, 0};
        if (lane < c) {
            const uint4* a = (const uint4*)&g_agg[(b * NCH + lane) * 8];
            uint4 a0 = a[0], a1 = a[1];
            A[0] = a0.x; A[1] = a0.y; A[2] = a0.z; A[3] = a0.w;
            A[4] = a1.x; A[5] = a1.y; A[6] = a1.z; A[7] = a1.w;
        }
        // reduce lanes 0..15 (lanes >= c contribute identity)
#pragma unroll
        for (int d = 8; d; d >>= 1) {
            uint32_t o[8];
#pragma unroll
            for (int w = 0; w < 8; ++w) o[w] = __shfl_down_sync(0xffffffffu, A[w], d, 16);
            A[0] |= o[0]; A[1] |= o[1]; A[2] |= o[2]; A[3] |= o[3]; A[4] |= o[4];
            A[5] = pmax(A[5], o[5]); A[6] = pmax(A[6], o[6]); A[7] = pmax(A[7], o[7]);
        }
        if (lane == 0) {
#pragma unroll
            for (int w = 0; w < 8; ++w) s_carry[w] = A[w];
        }
    }
    __syncthreads();

    int j = c * CH + tid;
    if (j < SS) {
        uint4* dst = (uint4*)&g_prefix[((size_t)b * 2048 + j) * 8];
        uint4 p0 = dst[0], p1 = dst[1];
        p0.x |= s_carry[0]; p0.y |= s_carry[1]; p0.z |= s_carry[2]; p0.w |= s_carry[3];
        p1.x |= s_carry[4];
        p1.y = pmax(p1.y, s_carry[5]);
        p1.z = pmax(p1.z, s_carry[6]);
        p1.w = pmax(p1.w, s_carry[7]);
        dst[0] = p0;
        dst[1] = p1;
    }
}

// Warp per row. PDL: argmax + copy run BEFORE the grid dependency sync
// (independent of the prefix); prefix-dependent params + overwrites after.
__global__ __launch_bounds__(256) void apply_kernel(const int* __restrict__ song,
                                                    const int* __restrict__ chosen,
                                                    const float* __restrict__ scores,
                                                    float* __restrict__ out) {
    int warp = threadIdx.x >> 5;
    int lane = threadIdx.x & 31;
    int row = blockIdx.x * 8 + warp;      // grid = 2047 -> 16376 rows exactly
    int b = row / SS;
    int i = row - b * SS;
    const float* srow = scores + (size_t)row * RT;
    float* orow = out + (size_t)row * RT;

    __shared__ int sp_all[8][16];
    int* sp = sp_all[warp];

    // --- lane 0: song/chosen loads (independent of front-end) ---
    int sm1 = 0, sb2 = 0, sp3 = 0, tcho = 0;
    if (lane == 0) {
        const int* si = song + (size_t)row * 11;
        sm1 = si[1]; sb2 = si[2]; sp3 = si[3];
        tcho = chosen[row];
    }

    // --- measure argmax over scores[0:256] (first-index tiebreak = jnp.argmax) ---
    float bv = srow[lane];
    int bi = lane;
#pragma unroll
    for (int k = 1; k < 8; ++k) {
        float v = srow[lane + 32 * k];
        if (v > bv) { bv = v; bi = lane + 32 * k; }
    }
#pragma unroll
    for (int d = 16; d; d >>= 1) {
        float ov = __shfl_down_sync(0xffffffffu, bv, d);
        int oi = __shfl_down_sync(0xffffffffu, bi, d);
        if (ov > bv || (ov == bv && oi < bi)) { bv = ov; bi = oi; }
    }
    int pred_m = bi;   // valid on lane 0

    // --- beat argmax over scores[256:272] ---
    float bb = srow[256 + (lane & 15)];
    int bj = lane & 15;
#pragma unroll
    for (int d = 8; d; d >>= 1) {
        float ov = __shfl_down_sync(0xffffffffu, bb, d, 16);
        int oj = __shfl_down_sync(0xffffffffu, bj, d, 16);
        if (ov > bb || (ov == bb && oj < bj)) { bb = ov; bj = oj; }
    }
    int pred_b = bj;   // valid on lane 0

    // --- float4 copy (row byte offset = row*4648; 16B-aligned iff row even) ---
    if ((row & 1) == 0) {
        const float4* s4 = (const float4*)srow;
        float4* o4 = (float4*)orow;
#pragma unroll
        for (int p = lane; p < 290; p += 32) o4[p] = s4[p];    // floats 0..1159
        if (lane == 0) *(float2*)(orow + 1160) = *(const float2*)(srow + 1160);
    } else {
        const float4* s4 = (const float4*)(srow + 2);
        float4* o4 = (float4*)(orow + 2);
#pragma unroll
        for (int p = lane; p < 290; p += 32) o4[p] = s4[p];    // floats 2..1161
        if (lane == 0) *(float2*)orow = *(const float2*)srow;
    }

    // --- wait for the front-end's prefix to be final ---
    cudaGridDependencySynchronize();

    if (lane == 0) {
        int jj = (i + 1 < SS) ? i + 1 : SS - 1;
        const uint4* PL = (const uint4*)&g_prefix[((size_t)b * 2048 + jj) * 8];
        uint4 p0 = PL[0], p1 = PL[1];
        uint32_t w0 = p0.x, w1 = p0.y, w2 = p0.z, w3 = p0.w, w4 = p1.x;
        uint32_t wk = p1.y, wt = p1.z, wp = p1.w;

        int last_ks = (int)(wk & 0xffu);
        int last_ts = (int)(wt & 0xffu);
        int last_tp = (int)(wp & 0xffu);
        bool has_ks = (wk >> 31) != 0;
        bool has_ts = (wt >> 31) != 0;
        int max_beat = c_num[last_ts % 12];

        bool c1f = (pred_m == sm1);
        int min_beat = c1f ? sb2 : 0;
        bool c2f = c1f && (pred_b == min_beat);
        int min_pos = c2f ? sp3 : 0;
        int min_m46 = (sb2 == 0 && sp3 == 0) ? sm1 : sm1 + 1;
        bool has_inst = (w0 | w1 | w2 | w3 | w4) != 0;
        bool is3 = (tcho == 3);

        sp[0] = (int)w0; sp[1] = (int)w1; sp[2] = (int)w2;
        sp[3] = (int)w3; sp[4] = (int)w4;
        sp[5] = is3 ? sm1 : ((tcho >= 4 && tcho <= 6) ? min_m46 : 0);
        sp[6] = is3 ? min_beat : 0;
        sp[7] = is3 ? max_beat : 16;
        sp[8] = is3 ? min_pos : 0;
        sp[9] = is3 ? 1 : ((tcho == 1 && has_inst) ? 2 : 0);
        sp[10] = is3 ? 1 : ((tcho == 4 && has_ks) ? 2 : 0);
        sp[11] = last_ks;
        sp[12] = is3 ? 1 : ((tcho == 5 && has_ts) ? 2 : 0);
        sp[13] = last_ts;
        sp[14] = is3 ? 1 : ((tcho == 6) ? 2 : 0);
        sp[15] = last_tp;
    }
    __syncwarp();

    // --- sparse overwrites (lane-strided) ---
    int mth = sp[5], blo = sp[6], bhi = sp[7], pth = sp[8];
    int imode = sp[9], kmode = sp[10], kval = sp[11];
    int tsm = sp[12], tsv = sp[13], tpm = sp[14], tpv = sp[15];

    for (int c = lane; c < mth; c += 32) orow[c] = NEGF;                 // measure
    if (lane < 16 && (lane < blo || lane >= bhi)) orow[256 + lane] = NEGF;  // beat
    for (int p = lane; p < pth; p += 32) orow[272 + p] = NEGF;           // position
    if (imode) {                                                          // instrument
#pragma unroll
        for (int k = 0; k < 5; ++k) {
            int ci = lane + 32 * k;
            if (ci < 129) {
                bool pres = ((uint32_t)sp[k] >> lane) & 1u;
                bool masked = (imode == 1) ? !pres : pres;
                if (masked) orow[784 + ci] = NEGF;
            }
        }
    }
    if (kmode && lane < 24) {                                             // key_sign
        bool masked = (kmode == 1) ? (lane != kval) : (lane == kval);
        if (masked) orow[1041 + lane] = NEGF;
    }
    if (tsm) {                                                            // time_sign
#pragma unroll
        for (int k = 0; k < 2; ++k) {
            int ct = lane + 32 * k;
            if (ct < 48) {
                bool masked = (tsm == 1) ? (ct != tsv) : (ct == tsv);
                if (masked) orow[1065 + ct] = NEGF;
            }
        }
    }
    if (tpm) {                                                            // tempo
#pragma unroll
        for (int k = 0; k < 2; ++k) {
            int cp = lane + 32 * k;
            if (cp < 49) {
                bool masked = (tpm == 1) ? (cp != tpv) : (cp == tpv);
                if (masked) orow[1113 + cp] = NEGF;
            }
        }
    }
}

extern "C" void kernel_launch(void* const* d_in, const int* in_sizes, int n_in,
                              void* d_out, int out_size) {
    const int* song = (const int*)d_in[0];
    const int* chosen = (const int*)d_in[1];
    const float* scores = (const float*)d_in[2];
    float* out = (float*)d_out;

    // scan_local: plain launch.
    scan_local<<<BB * NCH, CH>>>(song);

    // fold_carry + apply: programmatic dependent launches (overlap with
    // predecessor; cudaGridDependencySynchronize inside orders the reads).
    cudaLaunchAttribute attr[1];
    attr[0].id = cudaLaunchAttributeProgrammaticStreamSerialization;
    attr[0].val.programmaticStreamSerializationAllowed = 1;

    {
        cudaLaunchConfig_t cfg = {};
        cfg.gridDim = dim3(BB * (NCH - 1));
        cfg.blockDim = dim3(CH);
        cfg.attrs = attr;
        cfg.numAttrs = 1;
        cudaLaunchKernelEx(&cfg, fold_carry);
    }
    {
        cudaLaunchConfig_t cfg = {};
        cfg.gridDim = dim3(ROWS / 8);
        cfg.blockDim = dim3(256);
        cfg.attrs = attr;
        cfg.numAttrs = 1;
        cudaLaunchKernelEx(&cfg, apply_kernel, song, chosen, scores, out);
    }
}

// round 13
// speedup vs baseline: 1.1723x; 1.0423x over previous
#include <cuda_runtime.h>
#include <stdint.h>

#define BB 8
#define SS 2047
#define RT 1162
#define ROWS (BB * SS)
#define NEGF (-1e9f)
#define CH 128
#define NCH 16
#define GRID_APPLY 888                 // 6 blocks/SM x 148 SMs -> single wave
#define WARPS_TOTAL (GRID_APPLY * 8)   // 7104 warps, 2-3 rows each

// Prefix per (b, j), padded to 2048 rows per batch. After fold_carry it is the
// FINAL inclusive prefix.
// words 0..4 = instrument-present bitset (129 bits),
// word 5 = key_sign:  flag<<31 | j<<8 | value   (max selects latest; value inline)
// word 6 = time_sign: same encoding
// word 7 = tempo:     j<<8 | value, element j==0 always seeds its value
//          (matches jnp.argmax-of-zeros -> song[b,0,feat] semantics).
__device__ uint32_t g_prefix[(size_t)BB * 2048 * 8];
__device__ uint32_t g_agg[BB * NCH * 8];

__constant__ int c_num[12] = {1, 2, 3, 4, 5, 6, 7, 8, 9, 10, 12, 16};

__device__ __forceinline__ uint32_t pmax(uint32_t a, uint32_t b) { return a > b ? a : b; }

// 128 blocks (8 batches x 16 chunks) x 128 threads, 1 element/thread.
// Launched FIRST (plain) so its blocks get SM slots before apply fills up.
__global__ __launch_bounds__(128) void scan_local(const int* __restrict__ song) {
    cudaTriggerProgrammaticLaunchCompletion();   // let successors launch early

    int b = blockIdx.x >> 4;
    int c = blockIdx.x & 15;
    int tid = threadIdx.x, lane = tid & 31, warp = tid >> 5;
    int j = c * CH + tid;

    uint32_t S[8] = {0, 0, 0, 0, 0, 0, 0, 0};
    if (j < SS) {
        const int* e = song + ((size_t)b * SS + j) * 11;
        int ty = e[0];                 // all 5 loads issued together (MLP)
        int v6 = e[6];
        int v8 = e[8];
        int v9 = e[9];
        int v10 = e[10];
        if (ty == 1) {
            S[v6 >> 5] |= 1u << (v6 & 31);
        } else if (ty == 4) {
            S[5] = 0x80000000u | ((uint32_t)j << 8) | (uint32_t)v8;
        } else if (ty == 5) {
            S[6] = 0x80000000u | ((uint32_t)j << 8) | (uint32_t)v9;
        } else if (ty == 6) {
            S[7] = ((uint32_t)j << 8) | (uint32_t)v10;
        }
        if (j == 0) {   // seed: no-match default is index 0 -> its value
            S[5] = pmax(S[5], (uint32_t)v8);
            S[6] = pmax(S[6], (uint32_t)v9);
            S[7] = pmax(S[7], (uint32_t)v10);
        }
    }

#pragma unroll
    for (int d = 1; d < 32; d <<= 1) {
        uint32_t o[8];
#pragma unroll
        for (int w = 0; w < 8; ++w) o[w] = __shfl_up_sync(0xffffffffu, S[w], d);
        if (lane >= d) {
            S[0] |= o[0]; S[1] |= o[1]; S[2] |= o[2]; S[3] |= o[3]; S[4] |= o[4];
            S[5] = pmax(S[5], o[5]); S[6] = pmax(S[6], o[6]); S[7] = pmax(S[7], o[7]);
        }
    }

    __shared__ uint32_t agg[4][8];
    if (lane == 31) {
#pragma unroll
        for (int w = 0; w < 8; ++w) agg[warp][w] = S[w];
    }
    __syncthreads();
#pragma unroll
    for (int w2 = 0; w2 < 3; ++w2) {
        if (warp > w2) {
            S[0] |= agg[w2][0]; S[1] |= agg[w2][1]; S[2] |= agg[w2][2];
            S[3] |= agg[w2][3]; S[4] |= agg[w2][4];
            S[5] = pmax(S[5], agg[w2][5]);
            S[6] = pmax(S[6], agg[w2][6]);
            S[7] = pmax(S[7], agg[w2][7]);
        }
    }

    if (j < SS) {
        uint4* dst = (uint4*)&g_prefix[((size_t)b * 2048 + j) * 8];
        dst[0] = make_uint4(S[0], S[1], S[2], S[3]);
        dst[1] = make_uint4(S[4], S[5], S[6], S[7]);
    }
    int lastt = (c == NCH - 1) ? (SS - 1 - c * CH) : (CH - 1);
    if (tid == lastt) {
        uint4* a = (uint4*)&g_agg[(b * NCH + c) * 8];
        a[0] = make_uint4(S[0], S[1], S[2], S[3]);
        a[1] = make_uint4(S[4], S[5], S[6], S[7]);
    }
}

// 120 blocks. PSS: launches early, parks at the dependency sync, then folds
// carry into g_prefix in place -> FINAL.
__global__ __launch_bounds__(128) void fold_carry() {
    cudaTriggerProgrammaticLaunchCompletion();   // let apply launch immediately
    cudaGridDependencySynchronize();             // wait for scan_local completion

    int b = blockIdx.x / (NCH - 1);
    int c = blockIdx.x % (NCH - 1) + 1;    // 1..15
    int tid = threadIdx.x, lane = tid & 31, warp = tid >> 5;

    __shared__ uint32_t s_carry[8];

    if (warp == 0) {
        uint32_t A[8] = {0, 0, 0, 0, 0, 0, 0, 0};
        if (lane < c) {
            const uint4* a = (const uint4*)&g_agg[(b * NCH + lane) * 8];
            uint4 a0 = a[0], a1 = a[1];
            A[0] = a0.x; A[1] = a0.y; A[2] = a0.z; A[3] = a0.w;
            A[4] = a1.x; A[5] = a1.y; A[6] = a1.z; A[7] = a1.w;
        }
#pragma unroll
        for (int d = 8; d; d >>= 1) {
            uint32_t o[8];
#pragma unroll
            for (int w = 0; w < 8; ++w) o[w] = __shfl_down_sync(0xffffffffu, A[w], d, 16);
            A[0] |= o[0]; A[1] |= o[1]; A[2] |= o[2]; A[3] |= o[3]; A[4] |= o[4];
            A[5] = pmax(A[5], o[5]); A[6] = pmax(A[6], o[6]); A[7] = pmax(A[7], o[7]);
        }
        if (lane == 0) {
#pragma unroll
            for (int w = 0; w < 8; ++w) s_carry[w] = A[w];
        }
    }
    __syncthreads();

    int j = c * CH + tid;
    if (j < SS) {
        uint4* dst = (uint4*)&g_prefix[((size_t)b * 2048 + j) * 8];
        uint4 p0 = dst[0], p1 = dst[1];
        p0.x |= s_carry[0]; p0.y |= s_carry[1]; p0.z |= s_carry[2]; p0.w |= s_carry[3];
        p1.x |= s_carry[4];
        p1.y = pmax(p1.y, s_carry[5]);
        p1.z = pmax(p1.z, s_carry[6]);
        p1.w = pmax(p1.w, s_carry[7]);
        dst[0] = p0;
        dst[1] = p1;
    }
}

// Single-wave persistent apply: each warp owns 2-3 rows. Phase 1 (no deps):
// copy + argmax for ALL owned rows (~22us). Phase 2: one grid-dependency sync.
// Phase 3: params + sparse overwrites (lines L2-hot).
__global__ __launch_bounds__(256, 6) void apply_kernel(const int* __restrict__ song,
                                                       const int* __restrict__ chosen,
                                                       const float* __restrict__ scores,
                                                       float* __restrict__ out) {
    int warp = threadIdx.x >> 5;
    int lane = threadIdx.x & 31;
    int gw = blockIdx.x * 8 + warp;          // 0..7103

    __shared__ int sp_all[8][16];
    int* sp = sp_all[warp];

    int predm[3], predb[3];

    // ---- phase 1: copy + argmax for owned rows (independent of the scan) ----
#pragma unroll
    for (int k = 0; k < 3; ++k) {
        int row = gw + k * WARPS_TOTAL;
        predm[k] = 0; predb[k] = 0;
        if (row < ROWS) {
            const float* srow = scores + (size_t)row * RT;
            float* orow = out + (size_t)row * RT;

            // measure argmax over scores[0:256] (first-index tiebreak)
            float bv = srow[lane];
            int bi = lane;
#pragma unroll
            for (int q = 1; q < 8; ++q) {
                float v = srow[lane + 32 * q];
                if (v > bv) { bv = v; bi = lane + 32 * q; }
            }
#pragma unroll
            for (int d = 16; d; d >>= 1) {
                float ov = __shfl_down_sync(0xffffffffu, bv, d);
                int oi = __shfl_down_sync(0xffffffffu, bi, d);
                if (ov > bv || (ov == bv && oi < bi)) { bv = ov; bi = oi; }
            }
            predm[k] = bi;   // valid on lane 0

            // beat argmax over scores[256:272]
            float bb = srow[256 + (lane & 15)];
            int bj = lane & 15;
#pragma unroll
            for (int d = 8; d; d >>= 1) {
                float ov = __shfl_down_sync(0xffffffffu, bb, d, 16);
                int oj = __shfl_down_sync(0xffffffffu, bj, d, 16);
                if (ov > bb || (ov == bb && oj < bj)) { bb = ov; bj = oj; }
            }
            predb[k] = bj;   // valid on lane 0

            // float4 copy (row byte offset = row*4648; 16B-aligned iff row even)
            if ((row & 1) == 0) {
                const float4* s4 = (const float4*)srow;
                float4* o4 = (float4*)orow;
                for (int p = lane; p < 290; p += 32) o4[p] = s4[p];
                if (lane == 0) *(float2*)(orow + 1160) = *(const float2*)(srow + 1160);
            } else {
                const float4* s4 = (const float4*)(srow + 2);
                float4* o4 = (float4*)(orow + 2);
                for (int p = lane; p < 290; p += 32) o4[p] = s4[p];
                if (lane == 0) *(float2*)orow = *(const float2*)srow;
            }
        }
    }

    // ---- phase 2: wait for the front-end (scan+fold) to finish ----
    cudaGridDependencySynchronize();

    // ---- phase 3: params + sparse overwrites per owned row ----
#pragma unroll
    for (int k = 0; k < 3; ++k) {
        int row = gw + k * WARPS_TOTAL;
        if (row >= ROWS) break;
        int b = row / SS;
        int i = row - b * SS;
        float* orow = out + (size_t)row * RT;

        if (lane == 0) {
            int jj = (i + 1 < SS) ? i + 1 : SS - 1;
            const uint4* PL = (const uint4*)&g_prefix[((size_t)b * 2048 + jj) * 8];
            uint4 p0 = PL[0], p1 = PL[1];
            const int* si = song + (size_t)row * 11;
            int sm1 = si[1], sb2 = si[2], sp3 = si[3];
            int tcho = chosen[row];

            uint32_t w0 = p0.x, w1 = p0.y, w2 = p0.z, w3 = p0.w, w4 = p1.x;
            uint32_t wk = p1.y, wt = p1.z, wp = p1.w;

            int last_ks = (int)(wk & 0xffu);
            int last_ts = (int)(wt & 0xffu);
            int last_tp = (int)(wp & 0xffu);
            bool has_ks = (wk >> 31) != 0;
            bool has_ts = (wt >> 31) != 0;
            int max_beat = c_num[last_ts % 12];

            bool c1f = (predm[k] == sm1);
            int min_beat = c1f ? sb2 : 0;
            bool c2f = c1f && (predb[k] == min_beat);
            int min_pos = c2f ? sp3 : 0;
            int min_m46 = (sb2 == 0 && sp3 == 0) ? sm1 : sm1 + 1;
            bool has_inst = (w0 | w1 | w2 | w3 | w4) != 0;
            bool is3 = (tcho == 3);

            sp[0] = (int)w0; sp[1] = (int)w1; sp[2] = (int)w2;
            sp[3] = (int)w3; sp[4] = (int)w4;
            sp[5] = is3 ? sm1 : ((tcho >= 4 && tcho <= 6) ? min_m46 : 0);
            sp[6] = is3 ? min_beat : 0;
            sp[7] = is3 ? max_beat : 16;
            sp[8] = is3 ? min_pos : 0;
            sp[9] = is3 ? 1 : ((tcho == 1 && has_inst) ? 2 : 0);
            sp[10] = is3 ? 1 : ((tcho == 4 && has_ks) ? 2 : 0);
            sp[11] = last_ks;
            sp[12] = is3 ? 1 : ((tcho == 5 && has_ts) ? 2 : 0);
            sp[13] = last_ts;
            sp[14] = is3 ? 1 : ((tcho == 6) ? 2 : 0);
            sp[15] = last_tp;
        }
        __syncwarp();

        int mth = sp[5], blo = sp[6], bhi = sp[7], pth = sp[8];
        int imode = sp[9], kmode = sp[10], kval = sp[11];
        int tsm = sp[12], tsv = sp[13], tpm = sp[14], tpv = sp[15];

        for (int c = lane; c < mth; c += 32) orow[c] = NEGF;                 // measure
        if (lane < 16 && (lane < blo || lane >= bhi)) orow[256 + lane] = NEGF;  // beat
        for (int p = lane; p < pth; p += 32) orow[272 + p] = NEGF;           // position
        if (imode) {                                                          // instrument
#pragma unroll
            for (int q = 0; q < 5; ++q) {
                int ci = lane + 32 * q;
                if (ci < 129) {
                    bool pres = ((uint32_t)sp[q] >> lane) & 1u;
                    bool masked = (imode == 1) ? !pres : pres;
                    if (masked) orow[784 + ci] = NEGF;
                }
            }
        }
        if (kmode && lane < 24) {                                             // key_sign
            bool masked = (kmode == 1) ? (lane != kval) : (lane == kval);
            if (masked) orow[1041 + lane] = NEGF;
        }
        if (tsm) {                                                            // time_sign
#pragma unroll
            for (int q = 0; q < 2; ++q) {
                int ct = lane + 32 * q;
                if (ct < 48) {
                    bool masked = (tsm == 1) ? (ct != tsv) : (ct == tsv);
                    if (masked) orow[1065 + ct] = NEGF;
                }
            }
        }
        if (tpm) {                                                            // tempo
#pragma unroll
            for (int q = 0; q < 2; ++q) {
                int cp = lane + 32 * q;
                if (cp < 49) {
                    bool masked = (tpm == 1) ? (cp != tpv) : (cp == tpv);
                    if (masked) orow[1113 + cp] = NEGF;
                }
            }
        }
        __syncwarp();   // sp reused next k
    }
}

extern "C" void kernel_launch(void* const* d_in, const int* in_sizes, int n_in,
                              void* d_out, int out_size) {
    const int* song = (const int*)d_in[0];
    const int* chosen = (const int*)d_in[1];
    const float* scores = (const float*)d_in[2];
    float* out = (float*)d_out;

    // scan_local first (plain) so its blocks get SM slots before apply fills up.
    scan_local<<<BB * NCH, CH>>>(song);

    cudaLaunchAttribute attr[1];
    attr[0].id = cudaLaunchAttributeProgrammaticStreamSerialization;
    attr[0].val.programmaticStreamSerializationAllowed = 1;

    {   // fold_carry: PSS -> launches at scan entry, parks at its sync
        cudaLaunchConfig_t cfg = {};
        cfg.gridDim = dim3(BB * (NCH - 1));
        cfg.blockDim = dim3(CH);
        cfg.attrs = attr;
        cfg.numAttrs = 1;
        cudaLaunchKernelEx(&cfg, fold_carry);
    }
    {   // apply: PSS -> starts ~immediately; phase 1 (copy) overlaps scan+fold
        cudaLaunchConfig_t cfg = {};
        cfg.gridDim = dim3(GRID_APPLY);
        cfg.blockDim = dim3(256);
        cfg.attrs = attr;
        cfg.numAttrs = 1;
        cudaLaunchKernelEx(&cfg, apply_kernel, song, chosen, scores, out);
    }
}